// round 4
// baseline (speedup 1.0000x reference)
#include <cuda_runtime.h>
#include <mma.h>

using namespace nvcuda;
using tf32_t = wmma::precision::tf32;

// Problem constants
#define DMODEL 256
#define NHEAD  4
#define HD     64
#define NLAYER 8
#define DFF    1024
#define VOCAB  100
#define LT     256
#define BBATCH 2
#define FHH    32
#define FWW    256
#define SMEMN  (FHH*FWW)      // 8192 memory tokens
#define LB     (LT*BBATCH)    // 512 target rows
#define SBR    (SMEMN*BBATCH) // 16384 memory rows
#define BNH    (BBATCH*NHEAD) // 8 attention batches

#define LN10K 9.210340371976184f

// -------- scratch (device globals, allocation-free) --------
__device__ float g_mem[SBR*DMODEL];        // 16 MB
__device__ float g_ckv[2*SBR*DMODEL];      // 32 MB (ck, cv)
__device__ float g_scores[BNH*LT*SMEMN];   // 64 MB
__device__ float g_qkv[3*LB*DMODEL];
__device__ float g_tgt[LB*DMODEL];
__device__ float g_ao [LB*DMODEL];
__device__ float g_t2 [LB*DMODEL];
__device__ float g_ffh[LB*DFF];
__device__ float g_part[BNH*16*LT*HD];     // split-K partials (2.1M floats max)

// -------- memory tensor: features + 2D positional encoding --------
__global__ void mem_kernel(const float* __restrict__ features, float* __restrict__ mem) {
    int idx = blockIdx.x * 256 + threadIdx.x;
    int c   = idx & (DMODEL-1);
    int row = idx >> 8;            // s*B + b
    int b   = row & (BBATCH-1);
    int s   = row >> 1;
    int h   = s / FWW;
    int w   = s % FWW;
    float pe;
    if (c < DMODEL/2) {
        int e = c & ~1;
        float div = __expf(-(float)e / (float)DMODEL * LN10K);
        float arg = (float)h * div;
        pe = (c & 1) ? cosf(arg) : sinf(arg);
    } else {
        int e = (c - DMODEL/2) & ~1;
        float div = __expf(-(float)e / (float)DMODEL * LN10K);
        float arg = (float)w * div;
        pe = (c & 1) ? cosf(arg) : sinf(arg);
    }
    mem[idx] = features[(((size_t)b*DMODEL + c)*FHH + h)*FWW + w] + pe;
}

// -------- token embedding + 1D positional encoding --------
__global__ void embed_kernel(const int* __restrict__ tokens, const float* __restrict__ emb,
                             float* __restrict__ tgt) {
    int idx = blockIdx.x * 256 + threadIdx.x;
    int c   = idx & (DMODEL-1);
    int row = idx >> 8;            // l*B + b
    int l   = row >> 1;
    int tok = tokens[row];
    int e = c & ~1;
    float div = __expf(-(float)e / (float)DMODEL * LN10K);
    float arg = (float)l * div;
    float pe = (c & 1) ? cosf(arg) : sinf(arg);
    tgt[idx] = emb[(size_t)tok*DMODEL + c] + pe;
}

// ============================================================================
// wmma tf32 NT GEMM with 3xTF32 compensation.
// C = scale*(A[M,K] @ B[N,K]^T + bias), optional relu.
// CTA tile 64(m) x 128(n), 8 warps (2x4), warp tile 32x32, k-block 16.
// Batched via grid.z: z = batch*ksplit + ks.
//   ksplit==1: writes C[batch*cB + m*ldc + n] with bias/scale/relu.
//   ksplit>1 : writes raw partials at C + z*M*N (caller passes ldc=N).
// Requires: M%64==0, N%128==0, (K/ksplit)%16==0, 16B-aligned rows.
// ============================================================================
__global__ __launch_bounds__(256) void wgemm_nt(
    const float* __restrict__ A, int lda, int aB,
    const float* __restrict__ Bm, int ldb, int bB,
    const float* __restrict__ bias, int biasB,
    float* __restrict__ C, int ldc, int cB,
    int M, int N, int K, int ksplit, float scale, int relu)
{
    // union: As[64][20] (1280) + Bs[128][20] (2560) = 3840 floats during k-loop,
    // Os[64][132] (8448 floats) for the epilogue (after final sync).
    __shared__ __align__(16) float smem_u[8448];
    float (*As)[20]  = (float(*)[20])smem_u;
    float (*Bs)[20]  = (float(*)[20])(smem_u + 1280);
    float (*Os)[132] = (float(*)[132])smem_u;

    int ks = blockIdx.z % ksplit, batch = blockIdx.z / ksplit;
    A  += (size_t)batch * aB;
    Bm += (size_t)batch * bB;
    if (ksplit > 1) {
        C += (size_t)blockIdx.z * M * N;
    } else {
        C += (size_t)batch * cB;
        if (bias) bias += (size_t)batch * biasB;
    }
    int row0 = blockIdx.y * 64, col0 = blockIdx.x * 128;
    int tid = threadIdx.x;
    int wid = tid >> 5;
    int wm = wid >> 2, wn = wid & 3;

    wmma::fragment<wmma::accumulator, 16,16,8, float> cf[2][2];
    #pragma unroll
    for (int i=0;i<2;i++)
        #pragma unroll
        for (int j=0;j<2;j++) wmma::fill_fragment(cf[i][j], 0.0f);

    int kbeg = ks * (K/ksplit), kend = kbeg + K/ksplit;

    int am = tid >> 2, ac = (tid & 3) * 4;   // A: 64 rows x 4 float4 cols
    int bn = tid >> 2, bc = (tid & 3) * 4;   // B: rows bn and bn+64

    for (int k0 = kbeg; k0 < kend; k0 += 16) {
        *(float4*)&As[am][ac]    = *(const float4*)&A [(size_t)(row0+am)*lda + k0 + ac];
        *(float4*)&Bs[bn][bc]    = *(const float4*)&Bm[(size_t)(col0+bn)*ldb + k0 + bc];
        *(float4*)&Bs[bn+64][bc] = *(const float4*)&Bm[(size_t)(col0+bn+64)*ldb + k0 + bc];
        __syncthreads();
        #pragma unroll
        for (int kk = 0; kk < 2; kk++) {
            wmma::fragment<wmma::matrix_a, 16,16,8, tf32_t, wmma::row_major> ahi[2], alo[2];
            wmma::fragment<wmma::matrix_b, 16,16,8, tf32_t, wmma::col_major> bhi[2], blo[2];
            #pragma unroll
            for (int i=0;i<2;i++) {
                wmma::load_matrix_sync(ahi[i], &As[wm*32 + i*16][kk*8], 20);
                #pragma unroll
                for (int e=0;e<ahi[i].num_elements;e++) {
                    float v = ahi[i].x[e];
                    float h = wmma::__float_to_tf32(v);
                    ahi[i].x[e] = h;
                    alo[i].x[e] = wmma::__float_to_tf32(v - h);
                }
            }
            #pragma unroll
            for (int j=0;j<2;j++) {
                wmma::load_matrix_sync(bhi[j], &Bs[wn*32 + j*16][kk*8], 20);
                #pragma unroll
                for (int e=0;e<bhi[j].num_elements;e++) {
                    float v = bhi[j].x[e];
                    float h = wmma::__float_to_tf32(v);
                    bhi[j].x[e] = h;
                    blo[j].x[e] = wmma::__float_to_tf32(v - h);
                }
            }
            #pragma unroll
            for (int i=0;i<2;i++)
                #pragma unroll
                for (int j=0;j<2;j++) {
                    wmma::mma_sync(cf[i][j], ahi[i], bhi[j], cf[i][j]);
                    wmma::mma_sync(cf[i][j], ahi[i], blo[j], cf[i][j]);
                    wmma::mma_sync(cf[i][j], alo[i], bhi[j], cf[i][j]);
                }
        }
        __syncthreads();
    }

    // epilogue: stage to smem, then elementwise ops + write
    #pragma unroll
    for (int i=0;i<2;i++)
        #pragma unroll
        for (int j=0;j<2;j++)
            wmma::store_matrix_sync(&Os[wm*32+i*16][wn*32+j*16], cf[i][j], 132, wmma::mem_row_major);
    __syncthreads();

    #pragma unroll
    for (int it = 0; it < 8; it++) {
        int idx = it*256 + tid;            // float4 index over 64x32
        int m = idx >> 5;
        int c4 = (idx & 31) * 4;
        float4 v = *(float4*)&Os[m][c4];
        if (ksplit == 1) {
            if (bias) {
                v.x += bias[col0+c4];   v.y += bias[col0+c4+1];
                v.z += bias[col0+c4+2]; v.w += bias[col0+c4+3];
            }
            v.x *= scale; v.y *= scale; v.z *= scale; v.w *= scale;
            if (relu) {
                v.x = fmaxf(v.x, 0.f); v.y = fmaxf(v.y, 0.f);
                v.z = fmaxf(v.z, 0.f); v.w = fmaxf(v.w, 0.f);
            }
        }
        *(float4*)&C[(size_t)(row0+m)*ldc + col0 + c4] = v;
    }
}

// ============================================================================
// wmma tf32 NN GEMM (attn_probs @ V), split-K partials.
// P[z][M*N] = A[M,kslice] @ B[kslice,N], z = batch*ksplit + ks.
// CTA tile 64(m) x 64(n), 4 warps (2x2), 128 threads, k-block 16.
// Requires: M%64==0, N==64 per launch config here, (K/ksplit)%16==0.
// ============================================================================
__global__ __launch_bounds__(128) void wgemm_nn_sk(
    const float* __restrict__ A, int lda, int aB,
    const float* __restrict__ Bm, int ldb, int bB,
    float* __restrict__ P,
    int M, int N, int K, int ksplit)
{
    __shared__ __align__(16) float As[64][20];
    __shared__ __align__(16) float Bs[16][72];

    int ks = blockIdx.z % ksplit, batch = blockIdx.z / ksplit;
    A  += (size_t)batch * aB;
    Bm += (size_t)batch * bB;
    P  += (size_t)blockIdx.z * M * N;
    int kbeg = ks * (K/ksplit), kend = kbeg + K/ksplit;
    int row0 = blockIdx.y * 64, col0 = blockIdx.x * 64;
    int tid = threadIdx.x;
    int wid = tid >> 5;
    int wm = wid >> 1, wn = wid & 1;

    wmma::fragment<wmma::accumulator, 16,16,8, float> cf[2][2];
    #pragma unroll
    for (int i=0;i<2;i++)
        #pragma unroll
        for (int j=0;j<2;j++) wmma::fill_fragment(cf[i][j], 0.0f);

    for (int k0 = kbeg; k0 < kend; k0 += 16) {
        #pragma unroll
        for (int it=0; it<2; it++) {
            int idx = it*128 + tid;
            int m = idx >> 2, c4 = (idx & 3) * 4;
            *(float4*)&As[m][c4] = *(const float4*)&A[(size_t)(row0+m)*lda + k0 + c4];
        }
        #pragma unroll
        for (int it=0; it<2; it++) {
            int idx = it*128 + tid;
            int r = idx >> 4, c4 = (idx & 15) * 4;
            *(float4*)&Bs[r][c4] = *(const float4*)&Bm[(size_t)(k0+r)*ldb + col0 + c4];
        }
        __syncthreads();
        #pragma unroll
        for (int kk = 0; kk < 2; kk++) {
            wmma::fragment<wmma::matrix_a, 16,16,8, tf32_t, wmma::row_major> ahi[2], alo[2];
            wmma::fragment<wmma::matrix_b, 16,16,8, tf32_t, wmma::row_major> bhi[2], blo[2];
            #pragma unroll
            for (int i=0;i<2;i++) {
                wmma::load_matrix_sync(ahi[i], &As[wm*32 + i*16][kk*8], 20);
                #pragma unroll
                for (int e=0;e<ahi[i].num_elements;e++) {
                    float v = ahi[i].x[e];
                    float h = wmma::__float_to_tf32(v);
                    ahi[i].x[e] = h;
                    alo[i].x[e] = wmma::__float_to_tf32(v - h);
                }
            }
            #pragma unroll
            for (int j=0;j<2;j++) {
                wmma::load_matrix_sync(bhi[j], &Bs[kk*8][wn*32 + j*16], 72);
                #pragma unroll
                for (int e=0;e<bhi[j].num_elements;e++) {
                    float v = bhi[j].x[e];
                    float h = wmma::__float_to_tf32(v);
                    bhi[j].x[e] = h;
                    blo[j].x[e] = wmma::__float_to_tf32(v - h);
                }
            }
            #pragma unroll
            for (int i=0;i<2;i++)
                #pragma unroll
                for (int j=0;j<2;j++) {
                    wmma::mma_sync(cf[i][j], ahi[i], bhi[j], cf[i][j]);
                    wmma::mma_sync(cf[i][j], ahi[i], blo[j], cf[i][j]);
                    wmma::mma_sync(cf[i][j], alo[i], bhi[j], cf[i][j]);
                }
        }
        __syncthreads();
    }
    #pragma unroll
    for (int i=0;i<2;i++)
        #pragma unroll
        for (int j=0;j<2;j++)
            wmma::store_matrix_sync(&P[(size_t)(row0 + wm*32 + i*16)*N + col0 + wn*32 + j*16],
                                    cf[i][j], N, wmma::mem_row_major);
}

// -------- split-K reduce: C[batch*cB + m*ldc + n] = relu(sum_ks P + bias) --------
__global__ void reduce_sk(const float* __restrict__ P, float* __restrict__ C,
                          int ldc, int cB, int M, int N, int ksplit,
                          const float* __restrict__ bias, int biasB, int relu)
{
    int idx = blockIdx.x * 256 + threadIdx.x;   // over nbatch*M*N (exact multiple)
    int n = idx % N;
    int mb = idx / N;
    int m = mb % M;
    int batch = mb / M;
    const float* p = P + ((size_t)batch*ksplit)*M*N + (size_t)m*N + n;
    float s = 0.0f;
    for (int ksi = 0; ksi < ksplit; ksi++) s += p[(size_t)ksi*M*N];
    if (bias) s += bias[(size_t)batch*biasB + n];
    if (relu) s = fmaxf(s, 0.0f);
    C[(size_t)batch*cB + (size_t)m*ldc + n] = s;
}

// -------- SIMT NT GEMM (vocab projection only, N=100) --------
__global__ __launch_bounds__(256) void gemm_nt(
    const float* __restrict__ A, int lda,
    const float* __restrict__ Bm, int ldb,
    const float* __restrict__ bias,
    float* __restrict__ C, int ldc,
    int M, int N, int K)
{
    __shared__ float As[16][68];
    __shared__ float Bs[16][68];
    int row0 = blockIdx.y * 64, col0 = blockIdx.x * 64;
    int tid = threadIdx.x;
    int tx = tid & 15, ty = tid >> 4;
    int lc = tid & 15, lr = tid >> 4;
    float acc[4][4] = {};
    for (int k0 = 0; k0 < K; k0 += 16) {
        #pragma unroll
        for (int it = 0; it < 4; it++)
            As[lc][lr + it*16] = A[(size_t)(row0 + lr + it*16) * lda + k0 + lc];
        #pragma unroll
        for (int it = 0; it < 4; it++) {
            int n = col0 + lr + it*16;
            Bs[lc][lr + it*16] = (n < N) ? Bm[(size_t)n * ldb + k0 + lc] : 0.0f;
        }
        __syncthreads();
        #pragma unroll
        for (int kk = 0; kk < 16; kk++) {
            float4 av = *(const float4*)&As[kk][ty*4];
            float4 bv = *(const float4*)&Bs[kk][tx*4];
            acc[0][0] += av.x*bv.x; acc[0][1] += av.x*bv.y; acc[0][2] += av.x*bv.z; acc[0][3] += av.x*bv.w;
            acc[1][0] += av.y*bv.x; acc[1][1] += av.y*bv.y; acc[1][2] += av.y*bv.z; acc[1][3] += av.y*bv.w;
            acc[2][0] += av.z*bv.x; acc[2][1] += av.z*bv.y; acc[2][2] += av.z*bv.z; acc[2][3] += av.z*bv.w;
            acc[3][0] += av.w*bv.x; acc[3][1] += av.w*bv.y; acc[3][2] += av.w*bv.z; acc[3][3] += av.w*bv.w;
        }
        __syncthreads();
    }
    #pragma unroll
    for (int i = 0; i < 4; i++) {
        int m = row0 + ty*4 + i;
        #pragma unroll
        for (int j = 0; j < 4; j++) {
            int n = col0 + tx*4 + j;
            if (n < N) C[(size_t)m*ldc + n] = acc[i][j] + bias[n];
        }
    }
}

// -------- row softmax (optionally causal) --------
__global__ void softmax_kernel(float* __restrict__ sc, int Sx, int causal) {
    __shared__ float shm[8];
    int row = blockIdx.x;        // n*LT + l
    int l   = row & (LT-1);
    float* p = sc + (size_t)row * Sx;
    int limit = causal ? (l + 1) : Sx;
    int tid = threadIdx.x;

    float mx = -1e30f;
    for (int s = tid; s < limit; s += 256) mx = fmaxf(mx, p[s]);
    for (int o = 16; o; o >>= 1) mx = fmaxf(mx, __shfl_xor_sync(0xffffffffu, mx, o));
    if ((tid & 31) == 0) shm[tid >> 5] = mx;
    __syncthreads();
    if (tid < 32) {
        float t = (tid < 8) ? shm[tid] : -1e30f;
        for (int o = 4; o; o >>= 1) t = fmaxf(t, __shfl_xor_sync(0xffffffffu, t, o));
        if (tid == 0) shm[0] = t;
    }
    __syncthreads();
    mx = shm[0];
    __syncthreads();

    float sum = 0.0f;
    for (int s = tid; s < limit; s += 256) { float e = expf(p[s] - mx); p[s] = e; sum += e; }
    for (int o = 16; o; o >>= 1) sum += __shfl_xor_sync(0xffffffffu, sum, o);
    if ((tid & 31) == 0) shm[tid >> 5] = sum;
    __syncthreads();
    if (tid < 32) {
        float t = (tid < 8) ? shm[tid] : 0.0f;
        for (int o = 4; o; o >>= 1) t += __shfl_xor_sync(0xffffffffu, t, o);
        if (tid == 0) shm[0] = t;
    }
    __syncthreads();
    float inv = 1.0f / shm[0];
    for (int s = tid; s < Sx; s += 256) p[s] = (s < limit) ? p[s] * inv : 0.0f;
}

// -------- fused residual add + LayerNorm (in place on tgt) --------
__global__ void add_ln_kernel(float* __restrict__ tgt, const float* __restrict__ t2,
                              const float* __restrict__ g, const float* __restrict__ b) {
    __shared__ float shm[8];
    int row = blockIdx.x, c = threadIdx.x;
    size_t idx = (size_t)row * DMODEL + c;
    float x = tgt[idx] + t2[idx];

    float s = x;
    for (int o = 16; o; o >>= 1) s += __shfl_xor_sync(0xffffffffu, s, o);
    if ((c & 31) == 0) shm[c >> 5] = s;
    __syncthreads();
    if (c < 32) {
        float t = (c < 8) ? shm[c] : 0.0f;
        for (int o = 4; o; o >>= 1) t += __shfl_xor_sync(0xffffffffu, t, o);
        if (c == 0) shm[0] = t;
    }
    __syncthreads();
    float mean = shm[0] * (1.0f / DMODEL);
    __syncthreads();

    float d0 = x - mean;
    s = d0 * d0;
    for (int o = 16; o; o >>= 1) s += __shfl_xor_sync(0xffffffffu, s, o);
    if ((c & 31) == 0) shm[c >> 5] = s;
    __syncthreads();
    if (c < 32) {
        float t = (c < 8) ? shm[c] : 0.0f;
        for (int o = 4; o; o >>= 1) t += __shfl_xor_sync(0xffffffffu, t, o);
        if (c == 0) shm[0] = t;
    }
    __syncthreads();
    float var = shm[0] * (1.0f / DMODEL);
    tgt[idx] = d0 * rsqrtf(var + 1e-5f) * g[c] + b[c];
}

extern "C" void kernel_launch(void* const* d_in, const int* in_sizes, int n_in,
                              void* d_out, int out_size) {
    const int*   tokens   = (const int*)  d_in[0];
    const float* features = (const float*)d_in[1];
    const float* emb      = (const float*)d_in[2];
    const float* sa_w     = (const float*)d_in[3];
    const float* sa_b     = (const float*)d_in[4];
    const float* ca_w     = (const float*)d_in[5];
    const float* ca_b     = (const float*)d_in[6];
    const float* ln_g     = (const float*)d_in[7];
    const float* ln_b     = (const float*)d_in[8];
    const float* ff_w1    = (const float*)d_in[9];
    const float* ff_b1    = (const float*)d_in[10];
    const float* ff_w2    = (const float*)d_in[11];
    const float* ff_b2    = (const float*)d_in[12];
    const float* out_w    = (const float*)d_in[13];
    const float* out_b    = (const float*)d_in[14];
    float* out = (float*)d_out;

    float *mem, *ckv, *sc, *qkv, *tgt, *ao, *t2, *ffh, *part;
    cudaGetSymbolAddress((void**)&mem, g_mem);
    cudaGetSymbolAddress((void**)&ckv, g_ckv);
    cudaGetSymbolAddress((void**)&sc,  g_scores);
    cudaGetSymbolAddress((void**)&qkv, g_qkv);
    cudaGetSymbolAddress((void**)&tgt, g_tgt);
    cudaGetSymbolAddress((void**)&ao,  g_ao);
    cudaGetSymbolAddress((void**)&t2,  g_t2);
    cudaGetSymbolAddress((void**)&ffh, g_ffh);
    cudaGetSymbolAddress((void**)&part,g_part);

    float* q = qkv;
    float* k = qkv + (size_t)LB*DMODEL;
    float* v = qkv + (size_t)2*LB*DMODEL;
    float* ck = ckv;
    float* cv = ckv + (size_t)SBR*DMODEL;

    mem_kernel<<<(SBR*DMODEL)/256, 256>>>(features, mem);
    embed_kernel<<<(LB*DMODEL)/256, 256>>>(tokens, emb, tgt);

    const float qscale = 0.125f;   // 1/sqrt(64)
    const int DD = DMODEL*DMODEL;
    const int LDQ = BBATCH*DMODEL; // 512, row stride of q/k/v/ao over l

    for (int i = 0; i < NLAYER; i++) {
        const float* W  = sa_w + (size_t)i*4*DD;
        const float* Bi = sa_b + (size_t)i*4*DMODEL;

        // ---- self-attention ----
        // fused q,k,v projections: batch=3, split-K 4 -> partials, then reduce+bias
        wgemm_nt<<<dim3(DMODEL/128, LB/64, 3*4), 256>>>(
            tgt, DMODEL,0, W, DMODEL,DD, (const float*)0,0,
            part, DMODEL, 0, LB, DMODEL, DMODEL, 4, 1.0f, 0);
        reduce_sk<<<(3*LB*DMODEL)/256, 256>>>(part, qkv, DMODEL, LB*DMODEL, LB, DMODEL, 4,
                                              Bi, DMODEL, 0);
        // scores[n,l,s] = qscale * q.k   (batch over b*NH+h, head slice offset z*HD)
        wgemm_nt<<<dim3(LT/128, LT/64, BNH), 256>>>(
            q, LDQ, HD, k, LDQ, HD, (const float*)0,0,
            sc, LT, LT*LT, LT, LT, HD, 1, qscale, 0);
        softmax_kernel<<<BNH*LT, 256>>>(sc, LT, 1);
        // attn @ V, split-K 4
        wgemm_nn_sk<<<dim3(1, LT/64, BNH*4), 128>>>(sc, LT, LT*LT, v, LDQ, HD,
                                                    part, LT, HD, LT, 4);
        reduce_sk<<<(BNH*LT*HD)/256, 256>>>(part, ao, LDQ, HD, LT, HD, 4,
                                            (const float*)0, 0, 0);
        // out projection, split-K 4
        wgemm_nt<<<dim3(DMODEL/128, LB/64, 4), 256>>>(
            ao, DMODEL,0, W+3*DD, DMODEL,0, (const float*)0,0,
            part, DMODEL, 0, LB, DMODEL, DMODEL, 4, 1.0f, 0);
        reduce_sk<<<(LB*DMODEL)/256, 256>>>(part, t2, DMODEL, 0, LB, DMODEL, 4,
                                            Bi+3*DMODEL, 0, 0);
        add_ln_kernel<<<LB, DMODEL>>>(tgt, t2, ln_g + (size_t)(i*3+0)*DMODEL, ln_b + (size_t)(i*3+0)*DMODEL);

        // ---- cross-attention ----
        const float* Wc = ca_w + (size_t)i*4*DD;
        const float* Bc = ca_b + (size_t)i*4*DMODEL;
        // q projection, split-K 4
        wgemm_nt<<<dim3(DMODEL/128, LB/64, 4), 256>>>(
            tgt, DMODEL,0, Wc, DMODEL,0, (const float*)0,0,
            part, DMODEL, 0, LB, DMODEL, DMODEL, 4, 1.0f, 0);
        reduce_sk<<<(LB*DMODEL)/256, 256>>>(part, q, DMODEL, 0, LB, DMODEL, 4,
                                            Bc, 0, 0);
        // fused k,v projections of memory (batch 2, direct)
        wgemm_nt<<<dim3(DMODEL/128, SBR/64, 2), 256>>>(
            mem, DMODEL,0, Wc+DD, DMODEL,DD, Bc+DMODEL, DMODEL,
            ckv, DMODEL, SBR*DMODEL, SBR, DMODEL, DMODEL, 1, 1.0f, 0);
        // cross scores
        wgemm_nt<<<dim3(SMEMN/128, LT/64, BNH), 256>>>(
            q, LDQ, HD, ck, LDQ, HD, (const float*)0,0,
            sc, SMEMN, LT*SMEMN, LT, SMEMN, HD, 1, qscale, 0);
        softmax_kernel<<<BNH*LT, 256>>>(sc, SMEMN, 0);
        // attn @ V, split-K 16 over K=8192
        wgemm_nn_sk<<<dim3(1, LT/64, BNH*16), 128>>>(sc, SMEMN, LT*SMEMN, cv, LDQ, HD,
                                                     part, LT, HD, SMEMN, 16);
        reduce_sk<<<(BNH*LT*HD)/256, 256>>>(part, ao, LDQ, HD, LT, HD, 16,
                                            (const float*)0, 0, 0);
        // out projection, split-K 4
        wgemm_nt<<<dim3(DMODEL/128, LB/64, 4), 256>>>(
            ao, DMODEL,0, Wc+3*DD, DMODEL,0, (const float*)0,0,
            part, DMODEL, 0, LB, DMODEL, DMODEL, 4, 1.0f, 0);
        reduce_sk<<<(LB*DMODEL)/256, 256>>>(part, t2, DMODEL, 0, LB, DMODEL, 4,
                                            Bc+3*DMODEL, 0, 0);
        add_ln_kernel<<<LB, DMODEL>>>(tgt, t2, ln_g + (size_t)(i*3+1)*DMODEL, ln_b + (size_t)(i*3+1)*DMODEL);

        // ---- FFN ----
        wgemm_nt<<<dim3(DFF/128, LB/64, 1), 256>>>(
            tgt, DMODEL,0, ff_w1 + (size_t)i*DFF*DMODEL, DMODEL,0,
            ff_b1 + (size_t)i*DFF, 0,
            ffh, DFF, 0, LB, DFF, DMODEL, 1, 1.0f, 1);
        // FFN2 split-K 4 over K=1024
        wgemm_nt<<<dim3(DMODEL/128, LB/64, 4), 256>>>(
            ffh, DFF,0, ff_w2 + (size_t)i*DMODEL*DFF, DFF,0, (const float*)0,0,
            part, DMODEL, 0, LB, DMODEL, DFF, 4, 1.0f, 0);
        reduce_sk<<<(LB*DMODEL)/256, 256>>>(part, t2, DMODEL, 0, LB, DMODEL, 4,
                                            ff_b2 + (size_t)i*DMODEL, 0, 0);
        add_ln_kernel<<<LB, DMODEL>>>(tgt, t2, ln_g + (size_t)(i*3+2)*DMODEL, ln_b + (size_t)(i*3+2)*DMODEL);
    }

    // final vocab projection -> d_out [L,B,V]  (N=100, SIMT)
    gemm_nt<<<dim3((VOCAB+63)/64, LB/64), 256>>>(tgt, DMODEL, out_w, DMODEL, out_b,
                                                 out, VOCAB, LB, VOCAB, DMODEL);
}

// round 5
// speedup vs baseline: 1.8762x; 1.8762x over previous
#include <cuda_runtime.h>
#include <cuda_bf16.h>
#include <mma.h>

using namespace nvcuda;

// Problem constants
#define DMODEL 256
#define NHEAD  4
#define HD     64
#define NLAYER 8
#define DFF    1024
#define VOCAB  100
#define LT     256
#define BBATCH 2
#define FHH    32
#define FWW    256
#define SMEMN  (FHH*FWW)      // 8192 memory tokens
#define LB     (LT*BBATCH)    // 512 target rows
#define SBR    (SMEMN*BBATCH) // 16384 memory rows
#define BNH    (BBATCH*NHEAD) // 8 attention batches

#define LN10K 9.210340371976184f

// -------- scratch (device globals, allocation-free) --------
__device__ float g_mem[SBR*DMODEL];        // 16 MB
__device__ float g_ckv[2*SBR*DMODEL];      // 32 MB (ck, cv)
__device__ float g_scores[BNH*LT*SMEMN];   // 64 MB
__device__ float g_qkv[3*LB*DMODEL];
__device__ float g_tgt[LB*DMODEL];
__device__ float g_ao [LB*DMODEL];
__device__ float g_t2 [LB*DMODEL];
__device__ float g_ffh[LB*DFF];
__device__ float g_part[BNH*16*LT*HD];     // split-K partials

// -------- memory tensor: features + 2D positional encoding --------
__global__ void mem_kernel(const float* __restrict__ features, float* __restrict__ mem) {
    int idx = blockIdx.x * 256 + threadIdx.x;
    int c   = idx & (DMODEL-1);
    int row = idx >> 8;            // s*B + b
    int b   = row & (BBATCH-1);
    int s   = row >> 1;
    int h   = s / FWW;
    int w   = s % FWW;
    float pe;
    if (c < DMODEL/2) {
        int e = c & ~1;
        float div = __expf(-(float)e / (float)DMODEL * LN10K);
        float arg = (float)h * div;
        pe = (c & 1) ? cosf(arg) : sinf(arg);
    } else {
        int e = (c - DMODEL/2) & ~1;
        float div = __expf(-(float)e / (float)DMODEL * LN10K);
        float arg = (float)w * div;
        pe = (c & 1) ? cosf(arg) : sinf(arg);
    }
    mem[idx] = features[(((size_t)b*DMODEL + c)*FHH + h)*FWW + w] + pe;
}

// -------- token embedding + 1D positional encoding --------
__global__ void embed_kernel(const int* __restrict__ tokens, const float* __restrict__ emb,
                             float* __restrict__ tgt) {
    int idx = blockIdx.x * 256 + threadIdx.x;
    int c   = idx & (DMODEL-1);
    int row = idx >> 8;            // l*B + b
    int l   = row >> 1;
    int tok = tokens[row];
    int e = c & ~1;
    float div = __expf(-(float)e / (float)DMODEL * LN10K);
    float arg = (float)l * div;
    float pe = (c & 1) ? cosf(arg) : sinf(arg);
    tgt[idx] = emb[(size_t)tok*DMODEL + c] + pe;
}

__device__ __forceinline__ void split_bf16(float v, __nv_bfloat16& h, __nv_bfloat16& l) {
    h = __float2bfloat16(v);
    l = __float2bfloat16(v - __bfloat162float(h));
}

// ============================================================================
// bf16x3 NT GEMM: C = scale*(A[M,K] @ B[N,K]^T + bias), optional relu.
// hi/lo split done at smem staging; 3 bf16 MMAs per tile (hh + hl + lh).
// CTA tile 64(m) x 128(n), 8 warps (2x4), warp tile 32x32, k-block 16.
// grid.z = batch*ksplit + ks. ksplit>1 -> raw partials at C + z*M*N.
// Requires: M%64==0, N%128==0, (K/ksplit)%16==0.
// ============================================================================
__global__ __launch_bounds__(256) void wgemm_nt(
    const float* __restrict__ A, int lda, int aB,
    const float* __restrict__ Bm, int ldb, int bB,
    const float* __restrict__ bias, int biasB,
    float* __restrict__ C, int ldc, int cB,
    int M, int N, int K, int ksplit, float scale, int relu)
{
    // union: k-loop bf16 tiles (18KB) / epilogue Os[64][132] floats (33.8KB)
    __shared__ __align__(16) char smem_u[64*132*4];
    __nv_bfloat16 (*Ah)[24] = (__nv_bfloat16(*)[24])smem_u;                    // 3KB
    __nv_bfloat16 (*Al)[24] = (__nv_bfloat16(*)[24])(smem_u + 3072);
    __nv_bfloat16 (*Bh)[24] = (__nv_bfloat16(*)[24])(smem_u + 6144);           // 6KB
    __nv_bfloat16 (*Bl)[24] = (__nv_bfloat16(*)[24])(smem_u + 12288);
    float (*Os)[132] = (float(*)[132])smem_u;

    int ks = blockIdx.z % ksplit, batch = blockIdx.z / ksplit;
    A  += (size_t)batch * aB;
    Bm += (size_t)batch * bB;
    if (ksplit > 1) {
        C += (size_t)blockIdx.z * M * N;
    } else {
        C += (size_t)batch * cB;
        if (bias) bias += (size_t)batch * biasB;
    }
    int row0 = blockIdx.y * 64, col0 = blockIdx.x * 128;
    int tid = threadIdx.x;
    int wid = tid >> 5;
    int wm = wid >> 2, wn = wid & 3;

    wmma::fragment<wmma::accumulator, 16,16,16, float> cf[2][2];
    #pragma unroll
    for (int i=0;i<2;i++)
        #pragma unroll
        for (int j=0;j<2;j++) wmma::fill_fragment(cf[i][j], 0.0f);

    int kbeg = ks * (K/ksplit), kend = kbeg + K/ksplit;

    int am = tid >> 2, ac = (tid & 3) * 4;   // 64 rows x 4 float4

    for (int k0 = kbeg; k0 < kend; k0 += 16) {
        {
            float4 va = *(const float4*)&A[(size_t)(row0+am)*lda + k0 + ac];
            split_bf16(va.x, Ah[am][ac  ], Al[am][ac  ]);
            split_bf16(va.y, Ah[am][ac+1], Al[am][ac+1]);
            split_bf16(va.z, Ah[am][ac+2], Al[am][ac+2]);
            split_bf16(va.w, Ah[am][ac+3], Al[am][ac+3]);
            float4 v0 = *(const float4*)&Bm[(size_t)(col0+am)*ldb + k0 + ac];
            split_bf16(v0.x, Bh[am][ac  ], Bl[am][ac  ]);
            split_bf16(v0.y, Bh[am][ac+1], Bl[am][ac+1]);
            split_bf16(v0.z, Bh[am][ac+2], Bl[am][ac+2]);
            split_bf16(v0.w, Bh[am][ac+3], Bl[am][ac+3]);
            float4 v1 = *(const float4*)&Bm[(size_t)(col0+am+64)*ldb + k0 + ac];
            split_bf16(v1.x, Bh[am+64][ac  ], Bl[am+64][ac  ]);
            split_bf16(v1.y, Bh[am+64][ac+1], Bl[am+64][ac+1]);
            split_bf16(v1.z, Bh[am+64][ac+2], Bl[am+64][ac+2]);
            split_bf16(v1.w, Bh[am+64][ac+3], Bl[am+64][ac+3]);
        }
        __syncthreads();
        wmma::fragment<wmma::matrix_a, 16,16,16, __nv_bfloat16, wmma::row_major> ah[2], al[2];
        wmma::fragment<wmma::matrix_b, 16,16,16, __nv_bfloat16, wmma::col_major> bh[2], bl[2];
        #pragma unroll
        for (int i=0;i<2;i++) {
            wmma::load_matrix_sync(ah[i], &Ah[wm*32 + i*16][0], 24);
            wmma::load_matrix_sync(al[i], &Al[wm*32 + i*16][0], 24);
        }
        #pragma unroll
        for (int j=0;j<2;j++) {
            wmma::load_matrix_sync(bh[j], &Bh[wn*32 + j*16][0], 24);
            wmma::load_matrix_sync(bl[j], &Bl[wn*32 + j*16][0], 24);
        }
        #pragma unroll
        for (int i=0;i<2;i++)
            #pragma unroll
            for (int j=0;j<2;j++) {
                wmma::mma_sync(cf[i][j], ah[i], bh[j], cf[i][j]);
                wmma::mma_sync(cf[i][j], ah[i], bl[j], cf[i][j]);
                wmma::mma_sync(cf[i][j], al[i], bh[j], cf[i][j]);
            }
        __syncthreads();
    }

    // epilogue: stage to smem, then elementwise ops + float4 write
    #pragma unroll
    for (int i=0;i<2;i++)
        #pragma unroll
        for (int j=0;j<2;j++)
            wmma::store_matrix_sync(&Os[wm*32+i*16][wn*32+j*16], cf[i][j], 132, wmma::mem_row_major);
    __syncthreads();

    #pragma unroll
    for (int it = 0; it < 8; it++) {
        int idx = it*256 + tid;            // float4 index over 64x32
        int m = idx >> 5;
        int c4 = (idx & 31) * 4;
        float4 v = *(float4*)&Os[m][c4];
        if (ksplit == 1) {
            if (bias) {
                v.x += bias[col0+c4];   v.y += bias[col0+c4+1];
                v.z += bias[col0+c4+2]; v.w += bias[col0+c4+3];
            }
            v.x *= scale; v.y *= scale; v.z *= scale; v.w *= scale;
            if (relu) {
                v.x = fmaxf(v.x, 0.f); v.y = fmaxf(v.y, 0.f);
                v.z = fmaxf(v.z, 0.f); v.w = fmaxf(v.w, 0.f);
            }
        }
        *(float4*)&C[(size_t)(row0+m)*ldc + col0 + c4] = v;
    }
}

// ============================================================================
// bf16x3 NN GEMM (attn_probs @ V), split-K partials. P[z][M*N].
// CTA tile 64x64, 4 warps (2x2), 128 threads, k-block 16.
// ============================================================================
__global__ __launch_bounds__(128) void wgemm_nn_sk(
    const float* __restrict__ A, int lda, int aB,
    const float* __restrict__ Bm, int ldb, int bB,
    float* __restrict__ P,
    int M, int N, int K, int ksplit)
{
    __shared__ __align__(16) __nv_bfloat16 Ah[64][24], Al[64][24];  // 3KB each
    __shared__ __align__(16) __nv_bfloat16 Bh[16][72], Bl[16][72];  // 2.25KB each

    int ks = blockIdx.z % ksplit, batch = blockIdx.z / ksplit;
    A  += (size_t)batch * aB;
    Bm += (size_t)batch * bB;
    P  += (size_t)blockIdx.z * M * N;
    int kbeg = ks * (K/ksplit), kend = kbeg + K/ksplit;
    int row0 = blockIdx.y * 64, col0 = blockIdx.x * 64;
    int tid = threadIdx.x;
    int wid = tid >> 5;
    int wm = wid >> 1, wn = wid & 1;

    wmma::fragment<wmma::accumulator, 16,16,16, float> cf[2][2];
    #pragma unroll
    for (int i=0;i<2;i++)
        #pragma unroll
        for (int j=0;j<2;j++) wmma::fill_fragment(cf[i][j], 0.0f);

    for (int k0 = kbeg; k0 < kend; k0 += 16) {
        #pragma unroll
        for (int it=0; it<2; it++) {
            int idx = it*128 + tid;
            int m = idx >> 2, c4 = (idx & 3) * 4;
            float4 v = *(const float4*)&A[(size_t)(row0+m)*lda + k0 + c4];
            split_bf16(v.x, Ah[m][c4  ], Al[m][c4  ]);
            split_bf16(v.y, Ah[m][c4+1], Al[m][c4+1]);
            split_bf16(v.z, Ah[m][c4+2], Al[m][c4+2]);
            split_bf16(v.w, Ah[m][c4+3], Al[m][c4+3]);
        }
        #pragma unroll
        for (int it=0; it<2; it++) {
            int idx = it*128 + tid;
            int r = idx >> 4, c4 = (idx & 15) * 4;
            float4 v = *(const float4*)&Bm[(size_t)(k0+r)*ldb + col0 + c4];
            split_bf16(v.x, Bh[r][c4  ], Bl[r][c4  ]);
            split_bf16(v.y, Bh[r][c4+1], Bl[r][c4+1]);
            split_bf16(v.z, Bh[r][c4+2], Bl[r][c4+2]);
            split_bf16(v.w, Bh[r][c4+3], Bl[r][c4+3]);
        }
        __syncthreads();
        wmma::fragment<wmma::matrix_a, 16,16,16, __nv_bfloat16, wmma::row_major> ah[2], al[2];
        wmma::fragment<wmma::matrix_b, 16,16,16, __nv_bfloat16, wmma::row_major> bh[2], bl[2];
        #pragma unroll
        for (int i=0;i<2;i++) {
            wmma::load_matrix_sync(ah[i], &Ah[wm*32 + i*16][0], 24);
            wmma::load_matrix_sync(al[i], &Al[wm*32 + i*16][0], 24);
        }
        #pragma unroll
        for (int j=0;j<2;j++) {
            wmma::load_matrix_sync(bh[j], &Bh[0][wn*32 + j*16], 72);
            wmma::load_matrix_sync(bl[j], &Bl[0][wn*32 + j*16], 72);
        }
        #pragma unroll
        for (int i=0;i<2;i++)
            #pragma unroll
            for (int j=0;j<2;j++) {
                wmma::mma_sync(cf[i][j], ah[i], bh[j], cf[i][j]);
                wmma::mma_sync(cf[i][j], ah[i], bl[j], cf[i][j]);
                wmma::mma_sync(cf[i][j], al[i], bh[j], cf[i][j]);
            }
        __syncthreads();
    }
    #pragma unroll
    for (int i=0;i<2;i++)
        #pragma unroll
        for (int j=0;j<2;j++)
            wmma::store_matrix_sync(&P[(size_t)(row0 + wm*32 + i*16)*N + col0 + wn*32 + j*16],
                                    cf[i][j], N, wmma::mem_row_major);
}

// -------- split-K reduce: C[batch*cB + m*ldc + n] = relu(sum_ks P + bias) --------
__global__ void reduce_sk(const float* __restrict__ P, float* __restrict__ C,
                          int ldc, int cB, int M, int N, int ksplit,
                          const float* __restrict__ bias, int biasB, int relu)
{
    int idx = blockIdx.x * 256 + threadIdx.x;
    int n = idx % N;
    int mb = idx / N;
    int m = mb % M;
    int batch = mb / M;
    const float* p = P + ((size_t)batch*ksplit)*M*N + (size_t)m*N + n;
    float s = 0.0f;
    for (int ksi = 0; ksi < ksplit; ksi++) s += p[(size_t)ksi*M*N];
    if (bias) s += bias[(size_t)batch*biasB + n];
    if (relu) s = fmaxf(s, 0.0f);
    C[(size_t)batch*cB + (size_t)m*ldc + n] = s;
}

// -------- SIMT NT GEMM (vocab projection only, N=100) --------
__global__ __launch_bounds__(256) void gemm_nt(
    const float* __restrict__ A, int lda,
    const float* __restrict__ Bm, int ldb,
    const float* __restrict__ bias,
    float* __restrict__ C, int ldc,
    int M, int N, int K)
{
    __shared__ float As[16][68];
    __shared__ float Bs[16][68];
    int row0 = blockIdx.y * 64, col0 = blockIdx.x * 64;
    int tid = threadIdx.x;
    int tx = tid & 15, ty = tid >> 4;
    int lc = tid & 15, lr = tid >> 4;
    float acc[4][4] = {};
    for (int k0 = 0; k0 < K; k0 += 16) {
        #pragma unroll
        for (int it = 0; it < 4; it++)
            As[lc][lr + it*16] = A[(size_t)(row0 + lr + it*16) * lda + k0 + lc];
        #pragma unroll
        for (int it = 0; it < 4; it++) {
            int n = col0 + lr + it*16;
            Bs[lc][lr + it*16] = (n < N) ? Bm[(size_t)n * ldb + k0 + lc] : 0.0f;
        }
        __syncthreads();
        #pragma unroll
        for (int kk = 0; kk < 16; kk++) {
            float4 av = *(const float4*)&As[kk][ty*4];
            float4 bv = *(const float4*)&Bs[kk][tx*4];
            acc[0][0] += av.x*bv.x; acc[0][1] += av.x*bv.y; acc[0][2] += av.x*bv.z; acc[0][3] += av.x*bv.w;
            acc[1][0] += av.y*bv.x; acc[1][1] += av.y*bv.y; acc[1][2] += av.y*bv.z; acc[1][3] += av.y*bv.w;
            acc[2][0] += av.z*bv.x; acc[2][1] += av.z*bv.y; acc[2][2] += av.z*bv.z; acc[2][3] += av.z*bv.w;
            acc[3][0] += av.w*bv.x; acc[3][1] += av.w*bv.y; acc[3][2] += av.w*bv.z; acc[3][3] += av.w*bv.w;
        }
        __syncthreads();
    }
    #pragma unroll
    for (int i = 0; i < 4; i++) {
        int m = row0 + ty*4 + i;
        #pragma unroll
        for (int j = 0; j < 4; j++) {
            int n = col0 + tx*4 + j;
            if (n < N) C[(size_t)m*ldc + n] = acc[i][j] + bias[n];
        }
    }
}

// -------- register-cached one-pass softmax. Sx = PT*256 elements/row --------
template<int PT>
__global__ void softmax_reg(float* __restrict__ sc, int causal) {
    __shared__ float shm[8];
    int row = blockIdx.x;        // n*LT + l
    int l   = row & (LT-1);
    float* p = sc + (size_t)row * (PT*256);
    int limit = causal ? (l + 1) : PT*256;
    int tid = threadIdx.x;

    float vals[PT];
    float mx = -1e30f;
    #pragma unroll
    for (int i = 0; i < PT; i++) {
        int s = i*256 + tid;
        float v = p[s];
        vals[i] = v;
        if (s < limit) mx = fmaxf(mx, v);
    }
    for (int o = 16; o; o >>= 1) mx = fmaxf(mx, __shfl_xor_sync(0xffffffffu, mx, o));
    if ((tid & 31) == 0) shm[tid >> 5] = mx;
    __syncthreads();
    if (tid < 32) {
        float t = (tid < 8) ? shm[tid] : -1e30f;
        for (int o = 4; o; o >>= 1) t = fmaxf(t, __shfl_xor_sync(0xffffffffu, t, o));
        if (tid == 0) shm[0] = t;
    }
    __syncthreads();
    mx = shm[0];
    __syncthreads();

    float sum = 0.0f;
    #pragma unroll
    for (int i = 0; i < PT; i++) {
        int s = i*256 + tid;
        float e = (s < limit) ? expf(vals[i] - mx) : 0.0f;
        vals[i] = e;
        sum += e;
    }
    for (int o = 16; o; o >>= 1) sum += __shfl_xor_sync(0xffffffffu, sum, o);
    if ((tid & 31) == 0) shm[tid >> 5] = sum;
    __syncthreads();
    if (tid < 32) {
        float t = (tid < 8) ? shm[tid] : 0.0f;
        for (int o = 4; o; o >>= 1) t += __shfl_xor_sync(0xffffffffu, t, o);
        if (tid == 0) shm[0] = t;
    }
    __syncthreads();
    float inv = 1.0f / shm[0];
    #pragma unroll
    for (int i = 0; i < PT; i++)
        p[i*256 + tid] = vals[i] * inv;
}

// -------- fused residual add + LayerNorm (in place on tgt) --------
__global__ void add_ln_kernel(float* __restrict__ tgt, const float* __restrict__ t2,
                              const float* __restrict__ g, const float* __restrict__ b) {
    __shared__ float shm[8];
    int row = blockIdx.x, c = threadIdx.x;
    size_t idx = (size_t)row * DMODEL + c;
    float x = tgt[idx] + t2[idx];

    float s = x;
    for (int o = 16; o; o >>= 1) s += __shfl_xor_sync(0xffffffffu, s, o);
    if ((c & 31) == 0) shm[c >> 5] = s;
    __syncthreads();
    if (c < 32) {
        float t = (c < 8) ? shm[c] : 0.0f;
        for (int o = 4; o; o >>= 1) t += __shfl_xor_sync(0xffffffffu, t, o);
        if (c == 0) shm[0] = t;
    }
    __syncthreads();
    float mean = shm[0] * (1.0f / DMODEL);
    __syncthreads();

    float d0 = x - mean;
    s = d0 * d0;
    for (int o = 16; o; o >>= 1) s += __shfl_xor_sync(0xffffffffu, s, o);
    if ((c & 31) == 0) shm[c >> 5] = s;
    __syncthreads();
    if (c < 32) {
        float t = (c < 8) ? shm[c] : 0.0f;
        for (int o = 4; o; o >>= 1) t += __shfl_xor_sync(0xffffffffu, t, o);
        if (c == 0) shm[0] = t;
    }
    __syncthreads();
    float var = shm[0] * (1.0f / DMODEL);
    tgt[idx] = d0 * rsqrtf(var + 1e-5f) * g[c] + b[c];
}

extern "C" void kernel_launch(void* const* d_in, const int* in_sizes, int n_in,
                              void* d_out, int out_size) {
    const int*   tokens   = (const int*)  d_in[0];
    const float* features = (const float*)d_in[1];
    const float* emb      = (const float*)d_in[2];
    const float* sa_w     = (const float*)d_in[3];
    const float* sa_b     = (const float*)d_in[4];
    const float* ca_w     = (const float*)d_in[5];
    const float* ca_b     = (const float*)d_in[6];
    const float* ln_g     = (const float*)d_in[7];
    const float* ln_b     = (const float*)d_in[8];
    const float* ff_w1    = (const float*)d_in[9];
    const float* ff_b1    = (const float*)d_in[10];
    const float* ff_w2    = (const float*)d_in[11];
    const float* ff_b2    = (const float*)d_in[12];
    const float* out_w    = (const float*)d_in[13];
    const float* out_b    = (const float*)d_in[14];
    float* out = (float*)d_out;

    float *mem, *ckv, *sc, *qkv, *tgt, *ao, *t2, *ffh, *part;
    cudaGetSymbolAddress((void**)&mem, g_mem);
    cudaGetSymbolAddress((void**)&ckv, g_ckv);
    cudaGetSymbolAddress((void**)&sc,  g_scores);
    cudaGetSymbolAddress((void**)&qkv, g_qkv);
    cudaGetSymbolAddress((void**)&tgt, g_tgt);
    cudaGetSymbolAddress((void**)&ao,  g_ao);
    cudaGetSymbolAddress((void**)&t2,  g_t2);
    cudaGetSymbolAddress((void**)&ffh, g_ffh);
    cudaGetSymbolAddress((void**)&part,g_part);

    float* q = qkv;
    float* k = qkv + (size_t)LB*DMODEL;
    float* v = qkv + (size_t)2*LB*DMODEL;
    float* ck = ckv;
    float* cv = ckv + (size_t)SBR*DMODEL;

    mem_kernel<<<(SBR*DMODEL)/256, 256>>>(features, mem);
    embed_kernel<<<(LB*DMODEL)/256, 256>>>(tokens, emb, tgt);

    const float qscale = 0.125f;   // 1/sqrt(64)
    const int DD = DMODEL*DMODEL;
    const int LDQ = BBATCH*DMODEL; // 512, row stride of q/k/v/ao over l

    for (int i = 0; i < NLAYER; i++) {
        const float* W  = sa_w + (size_t)i*4*DD;
        const float* Bi = sa_b + (size_t)i*4*DMODEL;

        // ---- self-attention ----
        wgemm_nt<<<dim3(DMODEL/128, LB/64, 3*4), 256>>>(
            tgt, DMODEL,0, W, DMODEL,DD, (const float*)0,0,
            part, DMODEL, 0, LB, DMODEL, DMODEL, 4, 1.0f, 0);
        reduce_sk<<<(3*LB*DMODEL)/256, 256>>>(part, qkv, DMODEL, LB*DMODEL, LB, DMODEL, 4,
                                              Bi, DMODEL, 0);
        wgemm_nt<<<dim3(LT/128, LT/64, BNH), 256>>>(
            q, LDQ, HD, k, LDQ, HD, (const float*)0,0,
            sc, LT, LT*LT, LT, LT, HD, 1, qscale, 0);
        softmax_reg<1><<<BNH*LT, 256>>>(sc, 1);
        wgemm_nn_sk<<<dim3(1, LT/64, BNH*4), 128>>>(sc, LT, LT*LT, v, LDQ, HD,
                                                    part, LT, HD, LT, 4);
        reduce_sk<<<(BNH*LT*HD)/256, 256>>>(part, ao, LDQ, HD, LT, HD, 4,
                                            (const float*)0, 0, 0);
        wgemm_nt<<<dim3(DMODEL/128, LB/64, 4), 256>>>(
            ao, DMODEL,0, W+3*DD, DMODEL,0, (const float*)0,0,
            part, DMODEL, 0, LB, DMODEL, DMODEL, 4, 1.0f, 0);
        reduce_sk<<<(LB*DMODEL)/256, 256>>>(part, t2, DMODEL, 0, LB, DMODEL, 4,
                                            Bi+3*DMODEL, 0, 0);
        add_ln_kernel<<<LB, DMODEL>>>(tgt, t2, ln_g + (size_t)(i*3+0)*DMODEL, ln_b + (size_t)(i*3+0)*DMODEL);

        // ---- cross-attention ----
        const float* Wc = ca_w + (size_t)i*4*DD;
        const float* Bc = ca_b + (size_t)i*4*DMODEL;
        wgemm_nt<<<dim3(DMODEL/128, LB/64, 4), 256>>>(
            tgt, DMODEL,0, Wc, DMODEL,0, (const float*)0,0,
            part, DMODEL, 0, LB, DMODEL, DMODEL, 4, 1.0f, 0);
        reduce_sk<<<(LB*DMODEL)/256, 256>>>(part, q, DMODEL, 0, LB, DMODEL, 4,
                                            Bc, 0, 0);
        wgemm_nt<<<dim3(DMODEL/128, SBR/64, 2), 256>>>(
            mem, DMODEL,0, Wc+DD, DMODEL,DD, Bc+DMODEL, DMODEL,
            ckv, DMODEL, SBR*DMODEL, SBR, DMODEL, DMODEL, 1, 1.0f, 0);
        wgemm_nt<<<dim3(SMEMN/128, LT/64, BNH), 256>>>(
            q, LDQ, HD, ck, LDQ, HD, (const float*)0,0,
            sc, SMEMN, LT*SMEMN, LT, SMEMN, HD, 1, qscale, 0);
        softmax_reg<32><<<BNH*LT, 256>>>(sc, 0);
        wgemm_nn_sk<<<dim3(1, LT/64, BNH*16), 128>>>(sc, SMEMN, LT*SMEMN, cv, LDQ, HD,
                                                     part, LT, HD, SMEMN, 16);
        reduce_sk<<<(BNH*LT*HD)/256, 256>>>(part, ao, LDQ, HD, LT, HD, 16,
                                            (const float*)0, 0, 0);
        wgemm_nt<<<dim3(DMODEL/128, LB/64, 4), 256>>>(
            ao, DMODEL,0, Wc+3*DD, DMODEL,0, (const float*)0,0,
            part, DMODEL, 0, LB, DMODEL, DMODEL, 4, 1.0f, 0);
        reduce_sk<<<(LB*DMODEL)/256, 256>>>(part, t2, DMODEL, 0, LB, DMODEL, 4,
                                            Bc+3*DMODEL, 0, 0);
        add_ln_kernel<<<LB, DMODEL>>>(tgt, t2, ln_g + (size_t)(i*3+1)*DMODEL, ln_b + (size_t)(i*3+1)*DMODEL);

        // ---- FFN ----
        wgemm_nt<<<dim3(DFF/128, LB/64, 1), 256>>>(
            tgt, DMODEL,0, ff_w1 + (size_t)i*DFF*DMODEL, DMODEL,0,
            ff_b1 + (size_t)i*DFF, 0,
            ffh, DFF, 0, LB, DFF, DMODEL, 1, 1.0f, 1);
        wgemm_nt<<<dim3(DMODEL/128, LB/64, 4), 256>>>(
            ffh, DFF,0, ff_w2 + (size_t)i*DMODEL*DFF, DFF,0, (const float*)0,0,
            part, DMODEL, 0, LB, DMODEL, DFF, 4, 1.0f, 0);
        reduce_sk<<<(LB*DMODEL)/256, 256>>>(part, t2, DMODEL, 0, LB, DMODEL, 4,
                                            ff_b2 + (size_t)i*DMODEL, 0, 0);
        add_ln_kernel<<<LB, DMODEL>>>(tgt, t2, ln_g + (size_t)(i*3+2)*DMODEL, ln_b + (size_t)(i*3+2)*DMODEL);
    }

    // final vocab projection -> d_out [L,B,V]  (N=100, SIMT)
    gemm_nt<<<dim3((VOCAB+63)/64, LB/64), 256>>>(tgt, DMODEL, out_w, DMODEL, out_b,
                                                 out, VOCAB, LB, VOCAB, DMODEL);
}